// round 2
// baseline (speedup 1.0000x reference)
#include <cuda_runtime.h>
#include <cuda_bf16.h>
#include <stdint.h>

// Shapes (fixed):
//   updates: (8,128,128,256) float32 -> 33,554,432 elems
//   mask:    same shape int32, values in [0, 16,777,216)
//   output:  (8,256,256,256) float32 -> 134,217,728 elems
// out[mask[i] + (i/4194304)*4194304] += updates[i]; rest zeros.
// Max scatter index = 7*4194304 + 16777215 = 46,137,343.
//   -> head region [0, 46137344) must be zero BEFORE the scatter.
//   -> tail region [46137344, 134217728) is never touched by atomics:
//      zero it inside the scatter kernel (disjoint, order-free).

#define N_ELEMS      33554432u
#define N_VEC4       (N_ELEMS / 4u)          // 8,388,608 threads
#define BATCH_V4_SH  20                      // 2^20 vec4 per batch
#define BATCH_OFF_SH 22                      // 2^22 element batch offset
#define OUT_ELEMS    134217728u
#define HEAD_ELEMS   46137344u               // zeroed by memset before kernel
#define TAIL_ELEMS   (OUT_ELEMS - HEAD_ELEMS)    // 88,080,384
#define TAIL_V4      (TAIL_ELEMS / 4u)           // 22,020,096
#define HEAD_V4      (HEAD_ELEMS / 4u)           // 11,534,336

__global__ __launch_bounds__(256, 8)
void scatter_add_kernel(const float4* __restrict__ upd4,
                        const int4*  __restrict__ msk4,
                        float4* __restrict__ out4)
{
    unsigned int i = blockIdx.x * 256u + threadIdx.x;   // grid == N_VEC4 threads

    // Streaming loads (evict-first): don't let one-shot input traffic evict
    // the L2-resident scatter window.
    float4 u = __ldcs(upd4 + i);
    int4   m = __ldcs(msk4 + i);

    // Zero the untouched tail of the output (3 grid-strided float4 stores per
    // thread, streaming stores — overlapped with atomic latency / idle DRAM).
    const float4 z = make_float4(0.f, 0.f, 0.f, 0.f);
    #pragma unroll
    for (int k = 0; k < 3; k++) {
        unsigned int t = i + (unsigned int)k * N_VEC4;
        if (t < TAIL_V4) __stcs(out4 + HEAD_V4 + t, z);
    }

    // Scatter-add (RED.E.ADD.F32, no return).
    unsigned int base = (i >> BATCH_V4_SH) << BATCH_OFF_SH;
    float* out = (float*)out4;
    atomicAdd(out + base + (unsigned int)m.x, u.x);
    atomicAdd(out + base + (unsigned int)m.y, u.y);
    atomicAdd(out + base + (unsigned int)m.z, u.z);
    atomicAdd(out + base + (unsigned int)m.w, u.w);
}

extern "C" void kernel_launch(void* const* d_in, const int* in_sizes, int n_in,
                              void* d_out, int out_size)
{
    const float4* upd4 = (const float4*)d_in[0];
    const int4*   msk4 = (const int4*)d_in[1];

    // Zero only the head (possible scatter targets): 184 MB instead of 512 MB.
    cudaMemsetAsync(d_out, 0, (size_t)HEAD_ELEMS * sizeof(float), 0);

    const int threads = 256;
    const int blocks  = (int)(N_VEC4 / threads);   // 32768
    scatter_add_kernel<<<blocks, threads>>>(upd4, msk4, (float4*)d_out);
}